// round 3
// baseline (speedup 1.0000x reference)
#include <cuda_runtime.h>
#include <cuda_bf16.h>

// R2 retry: identical to R1 submission (R1 bench died to container infra failure,
// kernel never executed). valid_lens read as int32 (JAX x64-disabled downcast).

// Problem constants (fixed by the reference)
constexpr int B = 64;
constexpr int S = 1024;
constexpr int D = 64;
constexpr int QPB = 128;   // query rows per block == threads per block
constexpr int KT  = 64;    // key tile size

// Flash-attention, fp32, one thread per query row.
// Keys j >= valid_len contribute exp(-1e6 - m) == 0 in fp32 and are zeroed by
// the reference's second mask pass, so skipping them matches the reference.
__global__ __launch_bounds__(QPB, 2)
void attn_fp32_flash(const float* __restrict__ Q,
                     const float* __restrict__ K,
                     const float* __restrict__ V,
                     const int* __restrict__ lens,
                     float* __restrict__ O)
{
    __shared__ float Ks[KT * D];
    __shared__ float Vs[KT * D];

    const int b    = blockIdx.y;
    const int qrow = blockIdx.x * QPB + threadIdx.x;
    const int len  = lens[b];

    float* orow = O + ((size_t)b * S + qrow) * D;

    if (len <= 0) {
        // softmax weights are zeroed by the mask -> output row is exactly 0
        float4 z = make_float4(0.f, 0.f, 0.f, 0.f);
        float4* o4 = reinterpret_cast<float4*>(orow);
        #pragma unroll
        for (int i = 0; i < D / 4; i++) o4[i] = z;
        return;
    }

    // Load this thread's query row into registers, pre-scaled by 1/sqrt(D).
    float q[D];
    {
        const float4* q4 = reinterpret_cast<const float4*>(Q + ((size_t)b * S + qrow) * D);
        #pragma unroll
        for (int i = 0; i < D / 4; i++) {
            float4 t = q4[i];
            q[4*i+0] = t.x * 0.125f;
            q[4*i+1] = t.y * 0.125f;
            q[4*i+2] = t.z * 0.125f;
            q[4*i+3] = t.w * 0.125f;
        }
    }

    float o[D];
    #pragma unroll
    for (int i = 0; i < D; i++) o[i] = 0.f;
    float m = -1e30f;
    float l = 0.f;

    for (int jt = 0; jt < len; jt += KT) {
        __syncthreads();   // previous tile fully consumed
        {
            // Cooperative, coalesced tile load (KT*D floats = 1024 float4 each).
            const float4* Kg = reinterpret_cast<const float4*>(K + ((size_t)b * S + jt) * D);
            const float4* Vg = reinterpret_cast<const float4*>(V + ((size_t)b * S + jt) * D);
            float4* Ks4 = reinterpret_cast<float4*>(Ks);
            float4* Vs4 = reinterpret_cast<float4*>(Vs);
            for (int i = threadIdx.x; i < KT * D / 4; i += QPB) {
                Ks4[i] = Kg[i];
                Vs4[i] = Vg[i];
            }
        }
        __syncthreads();

        const int jend = min(KT, len - jt);
        for (int j = 0; j < jend; j++) {
            // s = <q, K_j>, 4 partial accumulators for ILP; K_j broadcast from smem.
            const float4* kr = reinterpret_cast<const float4*>(Ks + j * D);
            float s0 = 0.f, s1 = 0.f, s2 = 0.f, s3 = 0.f;
            #pragma unroll
            for (int i = 0; i < D / 4; i++) {
                float4 k = kr[i];
                s0 += q[4*i+0] * k.x;
                s1 += q[4*i+1] * k.y;
                s2 += q[4*i+2] * k.z;
                s3 += q[4*i+3] * k.w;
            }
            float s = (s0 + s1) + (s2 + s3);

            // Lazy rescale: new running max appears ~log(len) times per row.
            if (s > m) {
                float corr = __expf(m - s);   // exp(-inf)=0 handles first key
                m = s;
                l *= corr;
                #pragma unroll
                for (int i = 0; i < D; i++) o[i] *= corr;
            }

            float p = __expf(s - m);
            l += p;

            const float4* vr = reinterpret_cast<const float4*>(Vs + j * D);
            #pragma unroll
            for (int i = 0; i < D / 4; i++) {
                float4 v = vr[i];
                o[4*i+0] += p * v.x;
                o[4*i+1] += p * v.y;
                o[4*i+2] += p * v.z;
                o[4*i+3] += p * v.w;
            }
        }
    }

    const float inv = 1.0f / l;   // l >= 1 whenever len > 0
    float4* o4 = reinterpret_cast<float4*>(orow);
    #pragma unroll
    for (int i = 0; i < D / 4; i++) {
        float4 t;
        t.x = o[4*i+0] * inv;
        t.y = o[4*i+1] * inv;
        t.z = o[4*i+2] * inv;
        t.w = o[4*i+3] * inv;
        o4[i] = t;
    }
}

extern "C" void kernel_launch(void* const* d_in, const int* in_sizes, int n_in,
                              void* d_out, int out_size)
{
    const float* Qp = (const float*)d_in[0];
    const float* Kp = (const float*)d_in[1];
    const float* Vp = (const float*)d_in[2];
    const int*   Lp = (const int*)d_in[3];
    float*       Op = (float*)d_out;

    dim3 grid(S / QPB, B);
    attn_fp32_flash<<<grid, QPB>>>(Qp, Kp, Vp, Lp, Op);
}

// round 4
// speedup vs baseline: 1.1141x; 1.1141x over previous
#include <cuda_runtime.h>
#include <cuda_bf16.h>

// R3: packed f32x2 FMA (fma.rn.f32x2, PTX-only on sm_100a) for both hot loops.
// Structure otherwise identical to the R2 passing kernel (471us baseline).

constexpr int B = 64;
constexpr int S = 1024;
constexpr int D = 64;
constexpr int QPB = 128;   // query rows per block == threads per block
constexpr int KT  = 64;    // key tile size

using u64 = unsigned long long;

__device__ __forceinline__ u64 ffma2(u64 a, u64 b, u64 c) {
    u64 d;
    asm("fma.rn.f32x2 %0, %1, %2, %3;" : "=l"(d) : "l"(a), "l"(b), "l"(c));
    return d;
}
__device__ __forceinline__ u64 fmul2(u64 a, u64 b) {
    u64 d;
    asm("mul.rn.f32x2 %0, %1, %2;" : "=l"(d) : "l"(a), "l"(b));
    return d;
}
__device__ __forceinline__ u64 fadd2(u64 a, u64 b) {
    u64 d;
    asm("add.rn.f32x2 %0, %1, %2;" : "=l"(d) : "l"(a), "l"(b));
    return d;
}
__device__ __forceinline__ u64 pack2(float lo, float hi) {
    u64 r;
    asm("mov.b64 %0, {%1, %2};" : "=l"(r) : "f"(lo), "f"(hi));
    return r;
}
__device__ __forceinline__ void unpack2(u64 v, float& lo, float& hi) {
    asm("mov.b64 {%0, %1}, %2;" : "=f"(lo), "=f"(hi) : "l"(v));
}

__global__ __launch_bounds__(QPB, 2)
void attn_fp32x2_flash(const float* __restrict__ Q,
                       const float* __restrict__ K,
                       const float* __restrict__ V,
                       const int* __restrict__ lens,
                       float* __restrict__ O)
{
    __shared__ float Ks[KT * D];
    __shared__ float Vs[KT * D];

    const int b    = blockIdx.y;
    const int qrow = blockIdx.x * QPB + threadIdx.x;
    const int len  = lens[b];

    float* orow = O + ((size_t)b * S + qrow) * D;

    if (len <= 0) {
        float4 z = make_float4(0.f, 0.f, 0.f, 0.f);
        float4* o4 = reinterpret_cast<float4*>(orow);
        #pragma unroll
        for (int i = 0; i < D / 4; i++) o4[i] = z;
        return;
    }

    // Query row, packed as 32 x f32x2, pre-scaled by 1/sqrt(D).
    u64 q2[D / 2];
    {
        const u64 scale2 = pack2(0.125f, 0.125f);
        const ulonglong2* qg = reinterpret_cast<const ulonglong2*>(Q + ((size_t)b * S + qrow) * D);
        #pragma unroll
        for (int i = 0; i < D / 4; i++) {
            ulonglong2 t = qg[i];
            q2[2*i+0] = fmul2(t.x, scale2);
            q2[2*i+1] = fmul2(t.y, scale2);
        }
    }

    // Output accumulator, packed.
    u64 o2[D / 2];
    const u64 zero2 = pack2(0.f, 0.f);
    #pragma unroll
    for (int i = 0; i < D / 2; i++) o2[i] = zero2;
    float m = -1e30f;
    float l = 0.f;

    for (int jt = 0; jt < len; jt += KT) {
        __syncthreads();
        {
            const float4* Kg = reinterpret_cast<const float4*>(K + ((size_t)b * S + jt) * D);
            const float4* Vg = reinterpret_cast<const float4*>(V + ((size_t)b * S + jt) * D);
            float4* Ks4 = reinterpret_cast<float4*>(Ks);
            float4* Vs4 = reinterpret_cast<float4*>(Vs);
            for (int i = threadIdx.x; i < KT * D / 4; i += QPB) {
                Ks4[i] = Kg[i];
                Vs4[i] = Vg[i];
            }
        }
        __syncthreads();

        const int jend = min(KT, len - jt);
        for (int j = 0; j < jend; j++) {
            // s = <q, K_j> with 4 packed accumulators (8 fp32 lanes of ILP).
            const ulonglong2* kr = reinterpret_cast<const ulonglong2*>(Ks + j * D);
            u64 a0 = zero2, a1 = zero2, a2 = zero2, a3 = zero2;
            #pragma unroll
            for (int i = 0; i < D / 8; i++) {          // 8 iters, 16B x2 per iter
                ulonglong2 kA = kr[2*i];
                ulonglong2 kB = kr[2*i+1];
                a0 = ffma2(q2[4*i+0], kA.x, a0);
                a1 = ffma2(q2[4*i+1], kA.y, a1);
                a2 = ffma2(q2[4*i+2], kB.x, a2);
                a3 = ffma2(q2[4*i+3], kB.y, a3);
            }
            u64 sp = fadd2(fadd2(a0, a1), fadd2(a2, a3));
            float slo, shi;
            unpack2(sp, slo, shi);
            float s = slo + shi;

            // Lazy rescale: new running max ~log(len) times per row.
            if (s > m) {
                float corr = __expf(m - s);   // exp(-inf)=0 handles first key
                m = s;
                l *= corr;
                u64 corr2 = pack2(corr, corr);
                #pragma unroll
                for (int i = 0; i < D / 2; i++) o2[i] = fmul2(o2[i], corr2);
            }

            float p = __expf(s - m);
            l += p;
            u64 p2 = pack2(p, p);

            const ulonglong2* vr = reinterpret_cast<const ulonglong2*>(Vs + j * D);
            #pragma unroll
            for (int i = 0; i < D / 4; i++) {          // 16 iters of 16B
                ulonglong2 v = vr[i];
                o2[2*i+0] = ffma2(p2, v.x, o2[2*i+0]);
                o2[2*i+1] = ffma2(p2, v.y, o2[2*i+1]);
            }
        }
    }

    const float inv = 1.0f / l;
    const u64 inv2 = pack2(inv, inv);
    ulonglong2* og = reinterpret_cast<ulonglong2*>(orow);
    #pragma unroll
    for (int i = 0; i < D / 4; i++) {
        ulonglong2 t;
        t.x = fmul2(o2[2*i+0], inv2);
        t.y = fmul2(o2[2*i+1], inv2);
        og[i] = t;
    }
}

extern "C" void kernel_launch(void* const* d_in, const int* in_sizes, int n_in,
                              void* d_out, int out_size)
{
    const float* Qp = (const float*)d_in[0];
    const float* Kp = (const float*)d_in[1];
    const float* Vp = (const float*)d_in[2];
    const int*   Lp = (const int*)d_in[3];
    float*       Op = (float*)d_out;

    dim3 grid(S / QPB, B);
    attn_fp32x2_flash<<<grid, QPB>>>(Qp, Kp, Vp, Lp, Op);
}

// round 5
// speedup vs baseline: 1.2401x; 1.1132x over previous
#include <cuda_runtime.h>
#include <cuda_bf16.h>

// R4: 2-key unrolled inner loop (two independent score chains per thread) to
// cover LDS/MUFU/FMA dependency latency exposed at occ=11% / issue=39%.
// f32x2 packed math kept from R3 (423us baseline).

constexpr int B = 64;
constexpr int S = 1024;
constexpr int D = 64;
constexpr int QPB = 128;
constexpr int KT  = 64;

using u64 = unsigned long long;

__device__ __forceinline__ u64 ffma2(u64 a, u64 b, u64 c) {
    u64 d;
    asm("fma.rn.f32x2 %0, %1, %2, %3;" : "=l"(d) : "l"(a), "l"(b), "l"(c));
    return d;
}
__device__ __forceinline__ u64 fmul2(u64 a, u64 b) {
    u64 d;
    asm("mul.rn.f32x2 %0, %1, %2;" : "=l"(d) : "l"(a), "l"(b));
    return d;
}
__device__ __forceinline__ u64 fadd2(u64 a, u64 b) {
    u64 d;
    asm("add.rn.f32x2 %0, %1, %2;" : "=l"(d) : "l"(a), "l"(b));
    return d;
}
__device__ __forceinline__ u64 pack2(float lo, float hi) {
    u64 r;
    asm("mov.b64 %0, {%1, %2};" : "=l"(r) : "f"(lo), "f"(hi));
    return r;
}
__device__ __forceinline__ void unpack2(u64 v, float& lo, float& hi) {
    asm("mov.b64 {%0, %1}, %2;" : "=f"(lo), "=f"(hi) : "l"(v));
}

// Dot product of packed q with one K row from smem; 4 packed accumulators.
__device__ __forceinline__ float dot_row(const u64* q2, const float* krow) {
    const ulonglong2* kr = reinterpret_cast<const ulonglong2*>(krow);
    u64 a0 = 0, a1 = 0, a2 = 0, a3 = 0;
    #pragma unroll
    for (int i = 0; i < D / 8; i++) {
        ulonglong2 kA = kr[2*i];
        ulonglong2 kB = kr[2*i+1];
        a0 = ffma2(q2[4*i+0], kA.x, a0);
        a1 = ffma2(q2[4*i+1], kA.y, a1);
        a2 = ffma2(q2[4*i+2], kB.x, a2);
        a3 = ffma2(q2[4*i+3], kB.y, a3);
    }
    u64 sp = fadd2(fadd2(a0, a1), fadd2(a2, a3));
    float slo, shi;
    unpack2(sp, slo, shi);
    return slo + shi;
}

__global__ __launch_bounds__(QPB, 2)
void attn_fp32x2_flash2(const float* __restrict__ Q,
                        const float* __restrict__ K,
                        const float* __restrict__ V,
                        const int* __restrict__ lens,
                        float* __restrict__ O)
{
    __shared__ float Ks[KT * D];
    __shared__ float Vs[KT * D];

    const int b    = blockIdx.y;
    const int qrow = blockIdx.x * QPB + threadIdx.x;
    const int len  = lens[b];

    float* orow = O + ((size_t)b * S + qrow) * D;

    if (len <= 0) {
        float4 z = make_float4(0.f, 0.f, 0.f, 0.f);
        float4* o4 = reinterpret_cast<float4*>(orow);
        #pragma unroll
        for (int i = 0; i < D / 4; i++) o4[i] = z;
        return;
    }

    // Query row packed as 32 x f32x2, pre-scaled by 1/sqrt(D).
    u64 q2[D / 2];
    {
        const u64 scale2 = pack2(0.125f, 0.125f);
        const ulonglong2* qg = reinterpret_cast<const ulonglong2*>(Q + ((size_t)b * S + qrow) * D);
        #pragma unroll
        for (int i = 0; i < D / 4; i++) {
            ulonglong2 t = qg[i];
            q2[2*i+0] = fmul2(t.x, scale2);
            q2[2*i+1] = fmul2(t.y, scale2);
        }
    }

    u64 o2[D / 2];
    #pragma unroll
    for (int i = 0; i < D / 2; i++) o2[i] = 0;
    float m = -1e30f;
    float l = 0.f;

    for (int jt = 0; jt < len; jt += KT) {
        __syncthreads();
        {
            const float4* Kg = reinterpret_cast<const float4*>(K + ((size_t)b * S + jt) * D);
            const float4* Vg = reinterpret_cast<const float4*>(V + ((size_t)b * S + jt) * D);
            float4* Ks4 = reinterpret_cast<float4*>(Ks);
            float4* Vs4 = reinterpret_cast<float4*>(Vs);
            for (int i = threadIdx.x; i < KT * D / 4; i += QPB) {
                Ks4[i] = Kg[i];
                Vs4[i] = Vg[i];
            }
        }
        __syncthreads();

        const int jend = min(KT, len - jt);
        int j = 0;
        for (; j + 1 < jend; j += 2) {
            // Two independent score chains (ILP across the LDS->FMA->MUFU path).
            float sa = dot_row(q2, Ks + (j + 0) * D);
            float sb = dot_row(q2, Ks + (j + 1) * D);

            float smax = fmaxf(sa, sb);
            if (smax > m) {
                float corr = __expf(m - smax);   // exp(-inf)=0 on first pair
                m = smax;
                l *= corr;
                u64 corr2 = pack2(corr, corr);
                #pragma unroll
                for (int i = 0; i < D / 2; i++) o2[i] = fmul2(o2[i], corr2);
            }

            float pa = __expf(sa - m);
            float pb = __expf(sb - m);
            l += pa + pb;
            u64 pa2 = pack2(pa, pa);
            u64 pb2 = pack2(pb, pb);

            const ulonglong2* va = reinterpret_cast<const ulonglong2*>(Vs + (j + 0) * D);
            const ulonglong2* vb = reinterpret_cast<const ulonglong2*>(Vs + (j + 1) * D);
            #pragma unroll
            for (int i = 0; i < D / 4; i++) {
                ulonglong2 tva = va[i];
                ulonglong2 tvb = vb[i];
                o2[2*i+0] = ffma2(pa2, tva.x, o2[2*i+0]);
                o2[2*i+1] = ffma2(pa2, tva.y, o2[2*i+1]);
                o2[2*i+0] = ffma2(pb2, tvb.x, o2[2*i+0]);
                o2[2*i+1] = ffma2(pb2, tvb.y, o2[2*i+1]);
            }
        }
        if (j < jend) {                          // odd tail key
            float s = dot_row(q2, Ks + j * D);
            if (s > m) {
                float corr = __expf(m - s);
                m = s;
                l *= corr;
                u64 corr2 = pack2(corr, corr);
                #pragma unroll
                for (int i = 0; i < D / 2; i++) o2[i] = fmul2(o2[i], corr2);
            }
            float p = __expf(s - m);
            l += p;
            u64 p2 = pack2(p, p);
            const ulonglong2* vr = reinterpret_cast<const ulonglong2*>(Vs + j * D);
            #pragma unroll
            for (int i = 0; i < D / 4; i++) {
                ulonglong2 v = vr[i];
                o2[2*i+0] = ffma2(p2, v.x, o2[2*i+0]);
                o2[2*i+1] = ffma2(p2, v.y, o2[2*i+1]);
            }
        }
    }

    const float inv = 1.0f / l;
    const u64 inv2 = pack2(inv, inv);
    ulonglong2* og = reinterpret_cast<ulonglong2*>(orow);
    #pragma unroll
    for (int i = 0; i < D / 4; i++) {
        ulonglong2 t;
        t.x = fmul2(o2[2*i+0], inv2);
        t.y = fmul2(o2[2*i+1], inv2);
        og[i] = t;
    }
}

extern "C" void kernel_launch(void* const* d_in, const int* in_sizes, int n_in,
                              void* d_out, int out_size)
{
    const float* Qp = (const float*)d_in[0];
    const float* Kp = (const float*)d_in[1];
    const float* Vp = (const float*)d_in[2];
    const int*   Lp = (const int*)d_in[3];
    float*       Op = (float*)d_out;

    dim3 grid(S / QPB, B);
    attn_fp32x2_flash2<<<grid, QPB>>>(Qp, Kp, Vp, Lp, Op);
}